// round 16
// baseline (speedup 1.0000x reference)
#include <cuda_runtime.h>
#include <cuda_bf16.h>
#include <math.h>
#include <stdint.h>

#define NPTS 1024
#define DIM  64
#define HID  256
#define K    16
#define QB   8
#define RB   128
#define GRID 128
#define NT   512
#define SK   72          // bf16 row stride for MMA tiles (conflict-free ldmatrix)
#define SPLIT_PER_BLK 288   // (16384 + 16384 + 4096) / 128

__device__ float g_k[NPTS * DIM];
__device__ float g_v[NPTS * DIM];
__device__ unsigned g_bar;   // advances by GRID per launch
// pre-split bf16 weights (written cooperatively each launch, same values)
__device__ unsigned short g_A1hi[HID * DIM], g_A1lo[HID * DIM];   // [n*64+kd]
__device__ unsigned short g_A2hi[HID * DIM], g_A2lo[HID * DIM];   // [ch*4096+n*64+kk]
__device__ unsigned short g_P2hi[DIM * DIM], g_P2lo[DIM * DIM];   // [n*64+kk]

// ---- dynamic smem byte offsets ----
#define VG_OFF  0u          // 32768: fp32 VG[128][64]
#define A1_HI   32768u      // 36864: bf16 A1^T hi [256n][SK]
#define A1_LO   69632u      // 36864
#define A2_HI   106496u     // 36864: 4 chunk buffers of 9216 each, [64n][SK]
#define A2_LO   143360u     // 36864  (P2^T aliases chunk-3 slot during phase 1b)
#define EX      180224u     // 36864: ps / E bf16 hi+lo / fp32 T & C3 exchange
#define EX_ELO  198656u     // E lo half
#define SMEM_BYTES 217088u
#define PS_OFF  EX          // pos staging (12288)

// ---------------- helpers ----------------
__device__ __forceinline__ uint32_t smem_u32(const void* p) {
    uint32_t a;
    asm("{ .reg .u64 t; cvta.to.shared.u64 t, %1; cvt.u32.u64 %0, t; }" : "=r"(a) : "l"(p));
    return a;
}
__device__ __forceinline__ void bf16split(float v, unsigned short& hb, unsigned short& lb) {
    __nv_bfloat16 h = __float2bfloat16(v);
    hb = __bfloat16_as_ushort(h);
    __nv_bfloat16 l = __float2bfloat16(v - __bfloat162float(h));
    lb = __bfloat16_as_ushort(l);
}
__device__ __forceinline__ void split2(float x, float y, uint32_t& hi, uint32_t& lo) {
    unsigned short hx, lx, hy, ly;
    bf16split(x, hx, lx);
    bf16split(y, hy, ly);
    hi = (uint32_t)hx | ((uint32_t)hy << 16);
    lo = (uint32_t)lx | ((uint32_t)ly << 16);
}
__device__ __forceinline__ void ldsm4(uint32_t& r0, uint32_t& r1, uint32_t& r2, uint32_t& r3,
                                      uint32_t addr) {
    asm volatile("ldmatrix.sync.aligned.m8n8.x4.shared.b16 {%0,%1,%2,%3}, [%4];"
                 : "=r"(r0), "=r"(r1), "=r"(r2), "=r"(r3) : "r"(addr));
}
__device__ __forceinline__ void mma_bf16(float* c, const uint32_t* a, const uint32_t* b) {
    asm volatile("mma.sync.aligned.m16n8k16.row.col.f32.bf16.bf16.f32 "
                 "{%0,%1,%2,%3},{%4,%5,%6,%7},{%8,%9},{%0,%1,%2,%3};"
                 : "+f"(c[0]), "+f"(c[1]), "+f"(c[2]), "+f"(c[3])
                 : "r"(a[0]), "r"(a[1]), "r"(a[2]), "r"(a[3]), "r"(b[0]), "r"(b[1]));
}
__device__ __forceinline__ uint32_t a_addr(uint32_t base, int r0, int k0, int lane) {
    int row = r0 + (lane & 7) + ((lane >> 3) & 1) * 8;
    int col = k0 + (lane >> 4) * 8;
    return base + (uint32_t)(row * SK + col) * 2u;
}
__device__ __forceinline__ uint32_t b_addr(uint32_t base, int n0, int nfb, int k0, int lane) {
    int g = lane >> 3;
    int row = n0 + (nfb + (g >> 1)) * 8 + (lane & 7);
    int col = k0 + (g & 1) * 8;
    return base + (uint32_t)(row * SK + col) * 2u;
}

// ---------------------------------------------------------------------------
__global__ __launch_bounds__(NT)
void fused_kernel(const float* __restrict__ x,
                  const float* __restrict__ pos,
                  const float* __restrict__ Wq,
                  const float* __restrict__ Wk,
                  const float* __restrict__ Wv,
                  const float* __restrict__ P1, const float* __restrict__ pb1,
                  const float* __restrict__ P2, const float* __restrict__ pb2,
                  const float* __restrict__ A1, const float* __restrict__ ab1,
                  const float* __restrict__ A2, const float* __restrict__ ab2,
                  float* __restrict__ out) {
    extern __shared__ char smc[];
    float* VG  = (float*)(smc + VG_OFF);
    float* ps  = (float*)(smc + PS_OFF);
    float* EXf = (float*)(smc + EX);

    __shared__ int   nb[RB];
    __shared__ float rp[RB][3];
    __shared__ float qrow[QB * DIM];
    __shared__ float xs[QB * DIM];
    __shared__ float cval[QB][2][K];
    __shared__ int   cidx[QB][2][K];
    __shared__ unsigned s_ticket;

    int tid = threadIdx.x;
    int ib = blockIdx.x * QB;
    int w = tid >> 5, lane = tid & 31;
    uint32_t sb = smem_u32(smc);

    // ---- Prolog staging: pos, x rows ----
    for (int t = tid; t < NPTS * 3; t += NT) ps[t] = pos[t];
    for (int t = tid; t < QB * DIM; t += NT) xs[t] = x[ib * DIM + t];

    // ---- Weight split producer: this block's 1/128 slice of A1/A2/P2 ----
    if (tid < SPLIT_PER_BLK) {
        int g = blockIdx.x * SPLIT_PER_BLK + tid;
        float v; int idx;
        unsigned short hh, ll;
        if (g < 16384) {
            int n = g & 255, kd = g >> 8;
            v = A1[kd * HID + n];
            idx = n * 64 + kd;
            bf16split(v, hh, ll);
            g_A1hi[idx] = hh; g_A1lo[idx] = ll;
        } else if (g < 32768) {
            int u = g - 16384;
            int n = u & 63, kk = (u >> 6) & 63, ch = u >> 12;
            v = A2[(ch * 64 + kk) * DIM + n];
            idx = ch * 4096 + n * 64 + kk;
            bf16split(v, hh, ll);
            g_A2hi[idx] = hh; g_A2lo[idx] = ll;
        } else {
            int u = g - 32768;
            int n = u & 63, kk = u >> 6;
            v = P2[kk * DIM + n];
            idx = n * 64 + kk;
            bf16split(v, hh, ll);
            g_P2hi[idx] = hh; g_P2lo[idx] = ll;
        }
    }
    __syncthreads();

    // ---- qkv for this block's 8 rows (scalar; latency hidden pre-barrier) ----
    {
        int r = tid >> 6, d = tid & 63;
        float q = 0.f, kk = 0.f, vv = 0.f;
#pragma unroll 4
        for (int c = 0; c < DIM; c++) {
            float xv = xs[r * DIM + c];
            q  += xv * Wq[c * DIM + d];
            kk += xv * Wk[c * DIM + d];
            vv += xv * Wv[c * DIM + d];
        }
        qrow[r * DIM + d] = q;
        g_k[(ib + r) * DIM + d] = kk;
        g_v[(ib + r) * DIM + d] = vv;
    }
    __syncthreads();
    if (tid == 0) {
        __threadfence();
        s_ticket = atomicAdd(&g_bar, 1u);
    }

    // ---- kNN: 2 warps per query, 512 candidates each ----
    {
        int qq = w >> 1, hh = w & 1;
        int gi = ib + qq;
        float px = ps[gi * 3 + 0], py = ps[gi * 3 + 1], pz = ps[gi * 3 + 2];
        float v[16]; int id[16];
#pragma unroll
        for (int c = 0; c < 16; c++) {
            int j = hh * 512 + c * 32 + lane;
            float dx = px - ps[j * 3 + 0];
            float dy = py - ps[j * 3 + 1];
            float dz = pz - ps[j * 3 + 2];
            v[c] = dx * dx + dy * dy + dz * dz;
            id[c] = j;
        }
        for (int r = 0; r < K; r++) {
            float bv = v[0]; int bi = id[0];
#pragma unroll
            for (int c = 1; c < 16; c++)
                if (v[c] < bv || (v[c] == bv && id[c] < bi)) { bv = v[c]; bi = id[c]; }
#pragma unroll
            for (int off = 16; off > 0; off >>= 1) {
                float ov = __shfl_down_sync(0xffffffffu, bv, off);
                int   oi = __shfl_down_sync(0xffffffffu, bi, off);
                if (ov < bv || (ov == bv && oi < bi)) { bv = ov; bi = oi; }
            }
            bv = __shfl_sync(0xffffffffu, bv, 0);
            bi = __shfl_sync(0xffffffffu, bi, 0);
            if (lane == 0) { cval[qq][hh][r] = bv; cidx[qq][hh][r] = bi; }
#pragma unroll
            for (int c = 0; c < 16; c++) if (id[c] == bi) v[c] = 3.4e38f;
        }
    }
    __syncthreads();
    if ((w & 1) == 0) {
        int qq = w >> 1;
        float mv = cval[qq][lane >> 4][lane & 15];
        int   mi = cidx[qq][lane >> 4][lane & 15];
        for (int r = 0; r < K; r++) {
            float bv = mv; int bi = mi;
#pragma unroll
            for (int off = 16; off > 0; off >>= 1) {
                float ov = __shfl_down_sync(0xffffffffu, bv, off);
                int   oi = __shfl_down_sync(0xffffffffu, bi, off);
                if (ov < bv || (ov == bv && oi < bi)) { bv = ov; bi = oi; }
            }
            bi = __shfl_sync(0xffffffffu, bi, 0);
            if (lane == 0) nb[qq * K + r] = bi;
            if (mi == bi) mv = 3.4e38f;
        }
    }
    __syncthreads();

    for (int t = tid; t < RB * 3; t += NT) {
        int r = t / 3, c = t - r * 3;
        int gi = ib + (r >> 4);
        rp[r][c] = ps[gi * 3 + c] - ps[nb[r] * 3 + c];
    }
    __syncthreads();

    // ---- Phase 1a: E = relu(rp @ P1 + pb1) as bf16 split tiles (overwrites ps) ----
    for (int t = tid; t < RB * 64; t += NT) {
        int r = t >> 6, h = t & 63;
        float e = rp[r][0] * P1[h] + rp[r][1] * P1[64 + h]
                + rp[r][2] * P1[128 + h] + pb1[h];
        e = fmaxf(e, 0.f);
        unsigned short hh, ll; bf16split(e, hh, ll);
        uint32_t so = (uint32_t)(r * SK + h) * 2u;
        *(unsigned short*)(smc + EX + so) = hh;
        *(unsigned short*)(smc + EX_ELO + so) = ll;
    }
    if (tid == 0) {     // global barrier: k/v + split weights visible
        unsigned target = (s_ticket / GRID + 1u) * GRID;
        while ((int)(*(volatile unsigned*)&g_bar - target) < 0) { }
        __threadfence();
    }
    __syncthreads();

    // ---- Vectorized copies: A1^T full, A2 chunks 0-2, P2^T -> A2 chunk-3 slot ----
    {
        const uint4* a1h = (const uint4*)g_A1hi;
        const uint4* a1l = (const uint4*)g_A1lo;
        for (int t = tid; t < 2048; t += NT) {
            int l = t * 8;
            uint32_t off = (uint32_t)((l >> 6) * SK + (l & 63)) * 2u;
            *(uint4*)(smc + A1_HI + off) = a1h[t];
            *(uint4*)(smc + A1_LO + off) = a1l[t];
        }
        const uint4* a2h = (const uint4*)g_A2hi;
        const uint4* a2l = (const uint4*)g_A2lo;
        for (int t = tid; t < 1536; t += NT) {     // chunks 0..2
            int ch = t >> 9, tt = t & 511;
            int l = tt * 8;
            uint32_t off = (uint32_t)ch * 9216u + (uint32_t)((l >> 6) * SK + (l & 63)) * 2u;
            *(uint4*)(smc + A2_HI + off) = a2h[ch * 512 + tt];
            *(uint4*)(smc + A2_LO + off) = a2l[ch * 512 + tt];
        }
        const uint4* p2h = (const uint4*)g_P2hi;
        const uint4* p2l = (const uint4*)g_P2lo;
        for (int t = tid; t < 512; t += NT) {      // P2 -> chunk-3 slot
            int l = t * 8;
            uint32_t off = 3u * 9216u + (uint32_t)((l >> 6) * SK + (l & 63)) * 2u;
            *(uint4*)(smc + A2_HI + off) = p2h[t];
            *(uint4*)(smc + A2_LO + off) = p2l[t];
        }
    }
    __syncthreads();

    int q = w & 7, hh = w >> 3;
    int r0 = q * 16;
    int n0w = hh * 32;
    int rowA = r0 + (lane >> 2);
    int rowB = rowA + 8;

    uint32_t tHi[16], tLo[16];       // T A-fragments (4 k16 groups x 4 regs)

    // ---- Phase 1b (MMA): rpe = E @ P2 (P2 in chunk-3 slot) ----
    {
        float C1[16];
#pragma unroll
        for (int i = 0; i < 16; i++) C1[i] = 0.f;
        uint32_t pbh = sb + A2_HI + 3u * 9216u;
        uint32_t pbl = sb + A2_LO + 3u * 9216u;
#pragma unroll
        for (int ks = 0; ks < 4; ks++) {
            int k0 = ks * 16;
            uint32_t ah[4], al[4];
            ldsm4(ah[0], ah[1], ah[2], ah[3], a_addr(sb + EX, r0, k0, lane));
            ldsm4(al[0], al[1], al[2], al[3], a_addr(sb + EX_ELO, r0, k0, lane));
#pragma unroll
            for (int nfp = 0; nfp < 2; nfp++) {
                uint32_t bh[4], bl[4];
                ldsm4(bh[0], bh[1], bh[2], bh[3], b_addr(pbh, n0w, nfp * 2, k0, lane));
                ldsm4(bl[0], bl[1], bl[2], bl[3], b_addr(pbl, n0w, nfp * 2, k0, lane));
                mma_bf16(C1 + nfp * 8,     ah, bh);
                mma_bf16(C1 + nfp * 8,     ah, bl);
                mma_bf16(C1 + nfp * 8,     al, bh);
                mma_bf16(C1 + nfp * 8 + 4, ah, bh + 2);
                mma_bf16(C1 + nfp * 8 + 4, ah, bl + 2);
                mma_bf16(C1 + nfp * 8 + 4, al, bh + 2);
            }
        }
        __syncthreads();   // all E reads done; EX region is now reusable

        // epilogue: T = q - k + rpe ; VG = v + rpe ; T fp32 -> EX (stride 66)
        float tv[16];
        int j0 = nb[rowA], j1 = nb[rowB];
#pragma unroll
        for (int nf = 0; nf < 4; nf++) {
            int c = n0w + nf * 8 + 2 * (lane & 3);
            float2 b2 = *(const float2*)(pb2 + c);
            float2 qv = *(const float2*)(qrow + q * 64 + c);
            float2 k0v = *(const float2*)(g_k + j0 * 64 + c);
            float2 k1v = *(const float2*)(g_k + j1 * 64 + c);
            float2 v0v = *(const float2*)(g_v + j0 * 64 + c);
            float2 v1v = *(const float2*)(g_v + j1 * 64 + c);
            float rpe00 = C1[nf * 4 + 0] + b2.x, rpe01 = C1[nf * 4 + 1] + b2.y;
            float rpe10 = C1[nf * 4 + 2] + b2.x, rpe11 = C1[nf * 4 + 3] + b2.y;
            *(float2*)(VG + rowA * 64 + c) = make_float2(v0v.x + rpe00, v0v.y + rpe01);
            *(float2*)(VG + rowB * 64 + c) = make_float2(v1v.x + rpe10, v1v.y + rpe11);
            float t00 = qv.x - k0v.x + rpe00;
            float t01 = qv.y - k0v.y + rpe01;
            float t10 = qv.x - k1v.x + rpe10;
            float t11 = qv.y - k1v.y + rpe11;
            tv[nf * 4 + 0] = t00; tv[nf * 4 + 1] = t01;
            tv[nf * 4 + 2] = t10; tv[nf * 4 + 3] = t11;
            *(float2*)(EXf + rowA * 66 + c) = make_float2(t00, t01);
            *(float2*)(EXf + rowB * 66 + c) = make_float2(t10, t11);
        }
        // own-half T A-frags (constant register indices per branch)
#define OWN_FRAGS(off) { \
        split2(tv[0],  tv[1],  tHi[(off)+0], tLo[(off)+0]); \
        split2(tv[2],  tv[3],  tHi[(off)+1], tLo[(off)+1]); \
        split2(tv[4],  tv[5],  tHi[(off)+2], tLo[(off)+2]); \
        split2(tv[6],  tv[7],  tHi[(off)+3], tLo[(off)+3]); \
        split2(tv[8],  tv[9],  tHi[(off)+4], tLo[(off)+4]); \
        split2(tv[10], tv[11], tHi[(off)+5], tLo[(off)+5]); \
        split2(tv[12], tv[13], tHi[(off)+6], tLo[(off)+6]); \
        split2(tv[14], tv[15], tHi[(off)+7], tLo[(off)+7]); }
        if (hh == 0) OWN_FRAGS(0) else OWN_FRAGS(8)
    }
    // stage A2 chunk 3 (overwrites P2^T; all P2 reads done pre-sync below? —
    // P2 reads finished before the sync INSIDE phase 1b; safe to copy now)
    {
        const uint4* a2h = (const uint4*)(g_A2hi + 3 * 4096);
        const uint4* a2l = (const uint4*)(g_A2lo + 3 * 4096);
        for (int t = tid; t < 512; t += NT) {
            int l = t * 8;
            uint32_t off = 3u * 9216u + (uint32_t)((l >> 6) * SK + (l & 63)) * 2u;
            *(uint4*)(smc + A2_HI + off) = a2h[t];
            *(uint4*)(smc + A2_LO + off) = a2l[t];
        }
    }
    __syncthreads();   // T exchange + A2c3 visible

    // partner-half T A-frags from fp32 exchange
#define LOAD_PARTNER(kg) { \
        int kb = (kg) * 16 + 2 * (lane & 3); \
        float2 aA = *(const float2*)(EXf + rowA * 66 + kb); \
        float2 aB = *(const float2*)(EXf + rowB * 66 + kb); \
        float2 aC = *(const float2*)(EXf + rowA * 66 + kb + 8); \
        float2 aD = *(const float2*)(EXf + rowB * 66 + kb + 8); \
        split2(aA.x, aA.y, tHi[(kg)*4+0], tLo[(kg)*4+0]); \
        split2(aB.x, aB.y, tHi[(kg)*4+1], tLo[(kg)*4+1]); \
        split2(aC.x, aC.y, tHi[(kg)*4+2], tLo[(kg)*4+2]); \
        split2(aD.x, aD.y, tHi[(kg)*4+3], tLo[(kg)*4+3]); }
    if (hh == 0) { LOAD_PARTNER(2); LOAD_PARTNER(3); }
    else         { LOAD_PARTNER(0); LOAD_PARTNER(1); }

    // ---- Chunks: each warp does 2 hid-chunks, full 64 cols, all in registers ----
    float C3[32];
#pragma unroll
    for (int i = 0; i < 32; i++) C3[i] = 0.f;

#pragma unroll
    for (int cc = 0; cc < 2; cc++) {
        int ch = hh * 2 + cc;
        // Phase 2: C2 = T @ A1[:, ch*64 .. +64)
        float C2[32];
#pragma unroll
        for (int i = 0; i < 32; i++) C2[i] = 0.f;
#pragma unroll
        for (int ks = 0; ks < 4; ks++) {
            int k0 = ks * 16;
            const uint32_t* aH = tHi + ks * 4;
            const uint32_t* aL = tLo + ks * 4;
#pragma unroll
            for (int g = 0; g < 4; g++) {
                uint32_t bh[4], bl[4];
                ldsm4(bh[0], bh[1], bh[2], bh[3], b_addr(sb + A1_HI, ch * 64 + g * 16, 0, k0, lane));
                ldsm4(bl[0], bl[1], bl[2], bl[3], b_addr(sb + A1_LO, ch * 64 + g * 16, 0, k0, lane));
                mma_bf16(C2 + g * 8,     aH, bh);
                mma_bf16(C2 + g * 8,     aH, bl);
                mma_bf16(C2 + g * 8,     aL, bh);
                mma_bf16(C2 + g * 8 + 4, aH, bh + 2);
                mma_bf16(C2 + g * 8 + 4, aH, bl + 2);
                mma_bf16(C2 + g * 8 + 4, aL, bh + 2);
            }
        }
        // bias + relu + split -> H A-frags in registers (C output frag == A frag layout)
        uint32_t hHi[16], hLo[16];
#pragma unroll
        for (int g = 0; g < 4; g++) {
            int cb = ch * 64 + g * 16 + 2 * (lane & 3);
            float2 b0 = *(const float2*)(ab1 + cb);
            float2 b1 = *(const float2*)(ab1 + cb + 8);
            float v00 = fmaxf(C2[g * 8 + 0] + b0.x, 0.f);
            float v01 = fmaxf(C2[g * 8 + 1] + b0.y, 0.f);
            float v10 = fmaxf(C2[g * 8 + 2] + b0.x, 0.f);
            float v11 = fmaxf(C2[g * 8 + 3] + b0.y, 0.f);
            float u00 = fmaxf(C2[g * 8 + 4] + b1.x, 0.f);
            float u01 = fmaxf(C2[g * 8 + 5] + b1.y, 0.f);
            float u10 = fmaxf(C2[g * 8 + 6] + b1.x, 0.f);
            float u11 = fmaxf(C2[g * 8 + 7] + b1.y, 0.f);
            split2(v00, v01, hHi[g * 4 + 0], hLo[g * 4 + 0]);
            split2(v10, v11, hHi[g * 4 + 1], hLo[g * 4 + 1]);
            split2(u00, u01, hHi[g * 4 + 2], hLo[g * 4 + 2]);
            split2(u10, u11, hHi[g * 4 + 3], hLo[g * 4 + 3]);
        }
        // Phase 3: C3 += H_chunk @ A2_chunk (A from registers)
        uint32_t a2bh = sb + A2_HI + (uint32_t)ch * 9216u;
        uint32_t a2bl = sb + A2_LO + (uint32_t)ch * 9216u;
#pragma unroll
        for (int ks = 0; ks < 4; ks++) {
            int k0 = ks * 16;
            const uint32_t* aH = hHi + ks * 4;
            const uint32_t* aL = hLo + ks * 4;
#pragma unroll
            for (int g = 0; g < 4; g++) {
                uint32_t bh[4], bl[4];
                ldsm4(bh[0], bh[1], bh[2], bh[3], b_addr(a2bh, g * 16, 0, k0, lane));
                ldsm4(bl[0], bl[1], bl[2], bl[3], b_addr(a2bl, g * 16, 0, k0, lane));
                mma_bf16(C3 + g * 8,     aH, bh);
                mma_bf16(C3 + g * 8,     aH, bl);
                mma_bf16(C3 + g * 8,     aL, bh);
                mma_bf16(C3 + g * 8 + 4, aH, bh + 2);
                mma_bf16(C3 + g * 8 + 4, aH, bl + 2);
                mma_bf16(C3 + g * 8 + 4, aL, bh + 2);
            }
        }
    }

    // ---- C3 cross-warp reduction (hid halves) ----
    __syncthreads();   // all partner T-loads from EXf done; EXf reusable
    if (hh == 1) {
#pragma unroll
        for (int i = 0; i < 32; i++)
            EXf[q * 1024 + i * 32 + lane] = C3[i];
    }
    __syncthreads();

    // ---- Phase 4 on hh==0 warps: softmax over 16 neighbors, all 64 cols ----
    if (hh == 0) {
#pragma unroll
        for (int i = 0; i < 32; i++)
            C3[i] += EXf[q * 1024 + i * 32 + lane];
#pragma unroll
        for (int nf = 0; nf < 8; nf++) {
            int c = nf * 8 + 2 * (lane & 3);
            float2 b2 = *(const float2*)(ab2 + c);
            float s00 = C3[nf * 4 + 0] + b2.x;
            float s01 = C3[nf * 4 + 1] + b2.y;
            float s10 = C3[nf * 4 + 2] + b2.x;
            float s11 = C3[nf * 4 + 3] + b2.y;
            float m0 = fmaxf(s00, s10);
            float m1 = fmaxf(s01, s11);
#pragma unroll
            for (int msk = 4; msk <= 16; msk <<= 1) {
                m0 = fmaxf(m0, __shfl_xor_sync(0xffffffffu, m0, msk));
                m1 = fmaxf(m1, __shfl_xor_sync(0xffffffffu, m1, msk));
            }
            float e00 = __expf(s00 - m0), e10 = __expf(s10 - m0);
            float e01 = __expf(s01 - m1), e11 = __expf(s11 - m1);
            float2 vgA = *(const float2*)(VG + rowA * 64 + c);
            float2 vgB = *(const float2*)(VG + rowB * 64 + c);
            float sum0 = e00 + e10, sum1 = e01 + e11;
            float agg0 = e00 * vgA.x + e10 * vgB.x;
            float agg1 = e01 * vgA.y + e11 * vgB.y;
#pragma unroll
            for (int msk = 4; msk <= 16; msk <<= 1) {
                sum0 += __shfl_xor_sync(0xffffffffu, sum0, msk);
                sum1 += __shfl_xor_sync(0xffffffffu, sum1, msk);
                agg0 += __shfl_xor_sync(0xffffffffu, agg0, msk);
                agg1 += __shfl_xor_sync(0xffffffffu, agg1, msk);
            }
            if (lane < 4) {
                float2 o = make_float2(agg0 / sum0, agg1 / sum1);
                *(float2*)(out + (ib + q) * 64 + c) = o;
            }
        }
    }
}

// ---------------------------------------------------------------------------
extern "C" void kernel_launch(void* const* d_in, const int* in_sizes, int n_in,
                              void* d_out, int out_size) {
    const float* x   = (const float*)d_in[0];
    const float* pos = (const float*)d_in[1];
    const float* Wq  = (const float*)d_in[2];
    const float* Wk  = (const float*)d_in[3];
    const float* Wv  = (const float*)d_in[4];
    const float* P1  = (const float*)d_in[5];
    const float* pb1 = (const float*)d_in[6];
    const float* P2  = (const float*)d_in[7];
    const float* pb2 = (const float*)d_in[8];
    const float* A1  = (const float*)d_in[9];
    const float* ab1 = (const float*)d_in[10];
    const float* A2  = (const float*)d_in[11];
    const float* ab2 = (const float*)d_in[12];
    float* out = (float*)d_out;

    cudaFuncSetAttribute(fused_kernel, cudaFuncAttributeMaxDynamicSharedMemorySize,
                         SMEM_BYTES);
    fused_kernel<<<GRID, NT, SMEM_BYTES>>>(
        x, pos, Wq, Wk, Wv, P1, pb1, P2, pb2, A1, ab1, A2, ab2, out);
}

// round 17
// speedup vs baseline: 1.1606x; 1.1606x over previous
#include <cuda_runtime.h>
#include <cuda_bf16.h>
#include <math.h>
#include <stdint.h>

#define NPTS 1024
#define DIM  64
#define HID  256
#define K    16
#define QB   8
#define RB   128
#define GRID 128
#define NT   512
#define SK   72          // bf16 row stride for all MMA tiles (conflict-free ldmatrix)
#define SPLIT_PER_BLK 288   // (16384 + 16384 + 4096) / 128

__device__ float g_k[NPTS * DIM];
__device__ float g_v[NPTS * DIM];
__device__ unsigned g_bar;   // advances by GRID per launch
// pre-split bf16 weights (written cooperatively each launch, same values)
__device__ unsigned short g_A1hi[HID * DIM], g_A1lo[HID * DIM];   // [n*64+kd]
__device__ unsigned short g_A2hi[HID * DIM], g_A2lo[HID * DIM];   // [ch*4096+n*64+kk]
__device__ unsigned short g_P2hi[DIM * DIM], g_P2lo[DIM * DIM];   // [n*64+kk]

// ---- dynamic smem byte offsets ----
#define VG_OFF  0u          // 32768: fp32 VG[128][64]
#define TA_HI   32768u      // 18432: bf16 T hi [128][SK]
#define TA_LO   51200u      // 18432
#define A1_HI   69632u      // 36864: bf16 A1^T hi [256n][SK]
#define A1_LO   106496u     // 36864
#define A2C_HI  143360u     // 9216:  bf16 A2c^T / P2^T hi [64n][SK]
#define A2C_LO  152576u     // 9216
#define HC_HI   161792u     // 18432: bf16 H-chunk / E hi [128][SK]
#define HC_LO   180224u     // 18432
#define SMEM_BYTES 198656u
// prolog aliases
#define PS_OFF  HC_HI       // pos staging (12288)

// ---------------- helpers ----------------
__device__ __forceinline__ uint32_t smem_u32(const void* p) {
    uint32_t a;
    asm("{ .reg .u64 t; cvta.to.shared.u64 t, %1; cvt.u32.u64 %0, t; }" : "=r"(a) : "l"(p));
    return a;
}
__device__ __forceinline__ void bf16split(float v, unsigned short& hb, unsigned short& lb) {
    __nv_bfloat16 h = __float2bfloat16(v);
    hb = __bfloat16_as_ushort(h);
    __nv_bfloat16 l = __float2bfloat16(v - __bfloat162float(h));
    lb = __bfloat16_as_ushort(l);
}
__device__ __forceinline__ void split2(float x, float y, uint32_t& hi, uint32_t& lo) {
    unsigned short hx, lx, hy, ly;
    bf16split(x, hx, lx);
    bf16split(y, hy, ly);
    hi = (uint32_t)hx | ((uint32_t)hy << 16);
    lo = (uint32_t)lx | ((uint32_t)ly << 16);
}
__device__ __forceinline__ void ldsm4(uint32_t& r0, uint32_t& r1, uint32_t& r2, uint32_t& r3,
                                      uint32_t addr) {
    asm volatile("ldmatrix.sync.aligned.m8n8.x4.shared.b16 {%0,%1,%2,%3}, [%4];"
                 : "=r"(r0), "=r"(r1), "=r"(r2), "=r"(r3) : "r"(addr));
}
__device__ __forceinline__ void mma_bf16(float* c, const uint32_t* a, const uint32_t* b) {
    asm volatile("mma.sync.aligned.m16n8k16.row.col.f32.bf16.bf16.f32 "
                 "{%0,%1,%2,%3},{%4,%5,%6,%7},{%8,%9},{%0,%1,%2,%3};"
                 : "+f"(c[0]), "+f"(c[1]), "+f"(c[2]), "+f"(c[3])
                 : "r"(a[0]), "r"(a[1]), "r"(a[2]), "r"(a[3]), "r"(b[0]), "r"(b[1]));
}
__device__ __forceinline__ uint32_t a_addr(uint32_t base, int r0, int k0, int lane) {
    int row = r0 + (lane & 7) + ((lane >> 3) & 1) * 8;
    int col = k0 + (lane >> 4) * 8;
    return base + (uint32_t)(row * SK + col) * 2u;
}
__device__ __forceinline__ uint32_t b_addr(uint32_t base, int n0, int nfb, int k0, int lane) {
    int g = lane >> 3;
    int row = n0 + (nfb + (g >> 1)) * 8 + (lane & 7);
    int col = k0 + (g & 1) * 8;
    return base + (uint32_t)(row * SK + col) * 2u;
}

// ---------------------------------------------------------------------------
__global__ __launch_bounds__(NT)
void fused_kernel(const float* __restrict__ x,
                  const float* __restrict__ pos,
                  const float* __restrict__ Wq,
                  const float* __restrict__ Wk,
                  const float* __restrict__ Wv,
                  const float* __restrict__ P1, const float* __restrict__ pb1,
                  const float* __restrict__ P2, const float* __restrict__ pb2,
                  const float* __restrict__ A1, const float* __restrict__ ab1,
                  const float* __restrict__ A2, const float* __restrict__ ab2,
                  float* __restrict__ out) {
    extern __shared__ char smc[];
    float* VG  = (float*)(smc + VG_OFF);
    float* ps  = (float*)(smc + PS_OFF);

    __shared__ int   nb[RB];
    __shared__ float rp[RB][3];
    __shared__ float qrow[QB * DIM];
    __shared__ float xs[QB * DIM];
    __shared__ float cval[QB][2][K];
    __shared__ int   cidx[QB][2][K];
    __shared__ unsigned s_ticket;

    int tid = threadIdx.x;
    int ib = blockIdx.x * QB;
    int w = tid >> 5, lane = tid & 31;
    uint32_t sb = smem_u32(smc);

    // ---- Prolog staging: pos, x rows ----
    for (int t = tid; t < NPTS * 3; t += NT) ps[t] = pos[t];
    for (int t = tid; t < QB * DIM; t += NT) xs[t] = x[ib * DIM + t];

    // ---- Weight split producer: this block's 1/128 slice of A1/A2/P2 ----
    if (tid < SPLIT_PER_BLK) {
        int g = blockIdx.x * SPLIT_PER_BLK + tid;
        float v; int idx;
        unsigned short hh, ll;
        if (g < 16384) {
            int n = g & 255, kd = g >> 8;
            v = A1[kd * HID + n];
            idx = n * 64 + kd;
            bf16split(v, hh, ll);
            g_A1hi[idx] = hh; g_A1lo[idx] = ll;
        } else if (g < 32768) {
            int u = g - 16384;
            int n = u & 63, kk = (u >> 6) & 63, ch = u >> 12;
            v = A2[(ch * 64 + kk) * DIM + n];
            idx = ch * 4096 + n * 64 + kk;
            bf16split(v, hh, ll);
            g_A2hi[idx] = hh; g_A2lo[idx] = ll;
        } else {
            int u = g - 32768;
            int n = u & 63, kk = u >> 6;
            v = P2[kk * DIM + n];
            idx = n * 64 + kk;
            bf16split(v, hh, ll);
            g_P2hi[idx] = hh; g_P2lo[idx] = ll;
        }
    }
    __syncthreads();

    // ---- qkv for this block's 8 rows (scalar; latency hidden pre-barrier) ----
    {
        int r = tid >> 6, d = tid & 63;
        float q = 0.f, kk = 0.f, vv = 0.f;
#pragma unroll 8
        for (int c = 0; c < DIM; c++) {
            float xv = xs[r * DIM + c];
            q  += xv * Wq[c * DIM + d];
            kk += xv * Wk[c * DIM + d];
            vv += xv * Wv[c * DIM + d];
        }
        qrow[r * DIM + d] = q;
        g_k[(ib + r) * DIM + d] = kk;
        g_v[(ib + r) * DIM + d] = vv;
    }
    __syncthreads();
    if (tid == 0) {
        __threadfence();
        s_ticket = atomicAdd(&g_bar, 1u);
    }

    // ---- kNN: 2 warps per query, 512 candidates each ----
    {
        int qq = w >> 1, hh = w & 1;
        int gi = ib + qq;
        float px = ps[gi * 3 + 0], py = ps[gi * 3 + 1], pz = ps[gi * 3 + 2];
        float v[16];
#pragma unroll
        for (int c = 0; c < 16; c++) {
            int j = hh * 512 + c * 32 + lane;
            float dx = px - ps[j * 3 + 0];
            float dy = py - ps[j * 3 + 1];
            float dz = pz - ps[j * 3 + 2];
            v[c] = dx * dx + dy * dy + dz * dz;
        }
        for (int r = 0; r < K; r++) {
            // local argmin: strict < keeps lowest c (== lowest index) on ties
            float bv = v[0]; int bc = 0;
#pragma unroll
            for (int c = 1; c < 16; c++)
                if (v[c] < bv) { bv = v[c]; bc = c; }
            int bj = hh * 512 + bc * 32 + lane;
#pragma unroll
            for (int off = 16; off > 0; off >>= 1) {
                float ov = __shfl_down_sync(0xffffffffu, bv, off);
                int   oj = __shfl_down_sync(0xffffffffu, bj, off);
                if (ov < bv || (ov == bv && oj < bj)) { bv = ov; bj = oj; }
            }
            bv = __shfl_sync(0xffffffffu, bv, 0);
            bj = __shfl_sync(0xffffffffu, bj, 0);
            if (lane == 0) { cval[qq][hh][r] = bv; cidx[qq][hh][r] = bj; }
            // O(1) removal: j -> (lane, slot) is a bijection
            if ((bj & 31) == lane) v[(bj >> 5) & 15] = 3.4e38f;
        }
    }
    __syncthreads();
    // merge-path: two sorted 16-lists -> top-16 (keys (dist,idx) strictly ordered)
    if ((w & 1) == 0) {
        int qq = w >> 1;
        int side = lane >> 4;       // 0 = list A, 1 = list B
        int pos_ = lane & 15;
        float myv = cval[qq][side][pos_];
        int   myi = cidx[qq][side][pos_];
        const float* ov = cval[qq][side ^ 1];
        const int*   oi = cidx[qq][side ^ 1];
        int lo = 0, hi = 16;
#pragma unroll
        for (int step = 0; step < 5; step++) {
            if (lo < hi) {
                int mid = (lo + hi) >> 1;
                float mv = ov[mid]; int mi = oi[mid];
                bool less = (mv < myv) || (mv == myv && mi < myi);
                if (less) lo = mid + 1; else hi = mid;
            }
        }
        int rank = pos_ + lo;
        if (rank < K) nb[qq * K + rank] = myi;
    }
    __syncthreads();

    for (int t = tid; t < RB * 3; t += NT) {
        int r = t / 3, c = t - r * 3;
        int gi = ib + (r >> 4);
        rp[r][c] = ps[gi * 3 + c] - ps[nb[r] * 3 + c];
    }
    __syncthreads();

    // ---- Phase 1a: E = relu(rp @ P1 + pb1), packed 32-bit split stores ----
    for (int t = tid; t < RB * 32; t += NT) {
        int r = t >> 5, h = (t & 31) * 2;
        float r0v = rp[r][0], r1v = rp[r][1], r2v = rp[r][2];
        float e0 = r0v * P1[h]     + r1v * P1[64 + h]     + r2v * P1[128 + h]     + pb1[h];
        float e1 = r0v * P1[h + 1] + r1v * P1[64 + h + 1] + r2v * P1[128 + h + 1] + pb1[h + 1];
        e0 = fmaxf(e0, 0.f);
        e1 = fmaxf(e1, 0.f);
        uint32_t hi, lo; split2(e0, e1, hi, lo);
        uint32_t so = (uint32_t)(r * SK + h) * 2u;
        *(uint32_t*)(smc + HC_HI + so) = hi;
        *(uint32_t*)(smc + HC_LO + so) = lo;
    }
    if (tid == 0) {     // global barrier: k/v + split weights visible
        unsigned target = (s_ticket / GRID + 1u) * GRID;
        while ((int)(*(volatile unsigned*)&g_bar - target) < 0) { }
        __threadfence();
    }
    __syncthreads();

    // ---- Vectorized copies: P2^T -> A2C region, A1^T -> A1 region ----
    {
        const uint4* p2h = (const uint4*)g_P2hi;
        const uint4* p2l = (const uint4*)g_P2lo;
        for (int t = tid; t < 512; t += NT) {
            int l = t * 8;
            uint32_t off = (uint32_t)((l >> 6) * SK + (l & 63)) * 2u;
            *(uint4*)(smc + A2C_HI + off) = p2h[t];
            *(uint4*)(smc + A2C_LO + off) = p2l[t];
        }
        const uint4* a1h = (const uint4*)g_A1hi;
        const uint4* a1l = (const uint4*)g_A1lo;
        for (int t = tid; t < 2048; t += NT) {
            int l = t * 8;
            uint32_t off = (uint32_t)((l >> 6) * SK + (l & 63)) * 2u;
            *(uint4*)(smc + A1_HI + off) = a1h[t];
            *(uint4*)(smc + A1_LO + off) = a1l[t];
        }
    }
    __syncthreads();

    int r0 = (w & 7) * 16;           // query row-tile (16 rows = one query)
    int n0w = (w >> 3) * 32;         // 32-col half
    int rowA = r0 + (lane >> 2);
    int rowB = rowA + 8;

    // ---- Phase 1b (MMA): rpe = E @ P2 ; T(bf16 split) ; VG ----
    {
        float C1[16];
#pragma unroll
        for (int i = 0; i < 16; i++) C1[i] = 0.f;
#pragma unroll
        for (int ks = 0; ks < 4; ks++) {
            int k0 = ks * 16;
            uint32_t ah[4], al[4];
            ldsm4(ah[0], ah[1], ah[2], ah[3], a_addr(sb + HC_HI, r0, k0, lane));
            ldsm4(al[0], al[1], al[2], al[3], a_addr(sb + HC_LO, r0, k0, lane));
#pragma unroll
            for (int nfp = 0; nfp < 2; nfp++) {
                uint32_t bh[4], bl[4];
                ldsm4(bh[0], bh[1], bh[2], bh[3], b_addr(sb + A2C_HI, n0w, nfp * 2, k0, lane));
                ldsm4(bl[0], bl[1], bl[2], bl[3], b_addr(sb + A2C_LO, n0w, nfp * 2, k0, lane));
                mma_bf16(C1 + nfp * 8,     ah, bh);
                mma_bf16(C1 + nfp * 8,     ah, bl);
                mma_bf16(C1 + nfp * 8,     al, bh);
                mma_bf16(C1 + nfp * 8 + 4, ah, bh + 2);
                mma_bf16(C1 + nfp * 8 + 4, ah, bl + 2);
                mma_bf16(C1 + nfp * 8 + 4, al, bh + 2);
            }
        }
        // epilogue: T = q - k + rpe (split to TA), VG = v + rpe
        int qq = w & 7;
        int j0 = nb[rowA], j1 = nb[rowB];
#pragma unroll
        for (int nf = 0; nf < 4; nf++) {
            int c = n0w + nf * 8 + 2 * (lane & 3);
            float2 b2 = *(const float2*)(pb2 + c);
            float2 qv = *(const float2*)(qrow + qq * 64 + c);
            float2 k0v = *(const float2*)(g_k + j0 * 64 + c);
            float2 k1v = *(const float2*)(g_k + j1 * 64 + c);
            float2 v0v = *(const float2*)(g_v + j0 * 64 + c);
            float2 v1v = *(const float2*)(g_v + j1 * 64 + c);
            float rpe00 = C1[nf * 4 + 0] + b2.x, rpe01 = C1[nf * 4 + 1] + b2.y;
            float rpe10 = C1[nf * 4 + 2] + b2.x, rpe11 = C1[nf * 4 + 3] + b2.y;
            *(float2*)(VG + rowA * 64 + c) = make_float2(v0v.x + rpe00, v0v.y + rpe01);
            *(float2*)(VG + rowB * 64 + c) = make_float2(v1v.x + rpe10, v1v.y + rpe11);
            float t00 = qv.x - k0v.x + rpe00;
            float t01 = qv.y - k0v.y + rpe01;
            float t10 = qv.x - k1v.x + rpe10;
            float t11 = qv.y - k1v.y + rpe11;
            uint32_t hA, lA, hB, lB;
            split2(t00, t01, hA, lA);
            split2(t10, t11, hB, lB);
            uint32_t soA = (uint32_t)(rowA * SK + c) * 2u;
            uint32_t soB = (uint32_t)(rowB * SK + c) * 2u;
            *(uint32_t*)(smc + TA_HI + soA) = hA;
            *(uint32_t*)(smc + TA_LO + soA) = lA;
            *(uint32_t*)(smc + TA_HI + soB) = hB;
            *(uint32_t*)(smc + TA_LO + soB) = lB;
        }
    }
    __syncthreads();

    // ---- Chunked MMA: phases 2+3 over 4 chunks of 64 HID cols ----
    float C3[16];
#pragma unroll
    for (int i = 0; i < 16; i++) C3[i] = 0.f;

    for (int chunk = 0; chunk < 4; chunk++) {
        // vectorized copy of A2 chunk (chunk 0 overwrites P2^T — phase 1b done;
        // prior chunk's phase-3 A2C reads ordered by the loop-end sync)
        {
            const uint4* c2h = (const uint4*)(g_A2hi + chunk * 4096);
            const uint4* c2l = (const uint4*)(g_A2lo + chunk * 4096);
            for (int t = tid; t < 512; t += NT) {
                int l = t * 8;
                uint32_t off = (uint32_t)((l >> 6) * SK + (l & 63)) * 2u;
                *(uint4*)(smc + A2C_HI + off) = c2h[t];
                *(uint4*)(smc + A2C_LO + off) = c2l[t];
            }
        }

        // ---- Phase 2: C2 = T @ A1[:, chunk cols n0w..n0w+32) ----
        float C2[16];
#pragma unroll
        for (int i = 0; i < 16; i++) C2[i] = 0.f;
        int bn0 = chunk * 64 + n0w;
#pragma unroll
        for (int ks = 0; ks < 4; ks++) {
            int k0 = ks * 16;
            uint32_t ah[4], al[4];
            ldsm4(ah[0], ah[1], ah[2], ah[3], a_addr(sb + TA_HI, r0, k0, lane));
            ldsm4(al[0], al[1], al[2], al[3], a_addr(sb + TA_LO, r0, k0, lane));
#pragma unroll
            for (int nfp = 0; nfp < 2; nfp++) {
                uint32_t bh[4], bl[4];
                ldsm4(bh[0], bh[1], bh[2], bh[3], b_addr(sb + A1_HI, bn0, nfp * 2, k0, lane));
                ldsm4(bl[0], bl[1], bl[2], bl[3], b_addr(sb + A1_LO, bn0, nfp * 2, k0, lane));
                mma_bf16(C2 + nfp * 8,     ah, bh);
                mma_bf16(C2 + nfp * 8,     ah, bl);
                mma_bf16(C2 + nfp * 8,     al, bh);
                mma_bf16(C2 + nfp * 8 + 4, ah, bh + 2);
                mma_bf16(C2 + nfp * 8 + 4, ah, bl + 2);
                mma_bf16(C2 + nfp * 8 + 4, al, bh + 2);
            }
        }
        // (no sync here: phase-2 reads TA/A1; prior chunk's HC reads ordered
        //  by the loop-end sync)

        // bias + relu + bf16 split -> H chunk
        {
            int cbase = n0w + 2 * (lane & 3);
#pragma unroll
            for (int nf = 0; nf < 4; nf++) {
                int cl = cbase + nf * 8;
                float2 bias = *(const float2*)(ab1 + chunk * 64 + cl);
                float v00 = fmaxf(C2[nf * 4 + 0] + bias.x, 0.f);
                float v01 = fmaxf(C2[nf * 4 + 1] + bias.y, 0.f);
                float v10 = fmaxf(C2[nf * 4 + 2] + bias.x, 0.f);
                float v11 = fmaxf(C2[nf * 4 + 3] + bias.y, 0.f);
                uint32_t hA, lA, hB, lB;
                split2(v00, v01, hA, lA);
                split2(v10, v11, hB, lB);
                uint32_t soA = (uint32_t)(rowA * SK + cl) * 2u;
                uint32_t soB = (uint32_t)(rowB * SK + cl) * 2u;
                *(uint32_t*)(smc + HC_HI + soA) = hA;
                *(uint32_t*)(smc + HC_LO + soA) = lA;
                *(uint32_t*)(smc + HC_HI + soB) = hB;
                *(uint32_t*)(smc + HC_LO + soB) = lB;
            }
        }
        __syncthreads();

        // ---- Phase 3: C3 += H_chunk @ A2_chunk ----
#pragma unroll
        for (int ks = 0; ks < 4; ks++) {
            int k0 = ks * 16;
            uint32_t ah[4], al[4];
            ldsm4(ah[0], ah[1], ah[2], ah[3], a_addr(sb + HC_HI, r0, k0, lane));
            ldsm4(al[0], al[1], al[2], al[3], a_addr(sb + HC_LO, r0, k0, lane));
#pragma unroll
            for (int nfp = 0; nfp < 2; nfp++) {
                uint32_t bh[4], bl[4];
                ldsm4(bh[0], bh[1], bh[2], bh[3], b_addr(sb + A2C_HI, n0w, nfp * 2, k0, lane));
                ldsm4(bl[0], bl[1], bl[2], bl[3], b_addr(sb + A2C_LO, n0w, nfp * 2, k0, lane));
                mma_bf16(C3 + nfp * 8,     ah, bh);
                mma_bf16(C3 + nfp * 8,     ah, bl);
                mma_bf16(C3 + nfp * 8,     al, bh);
                mma_bf16(C3 + nfp * 8 + 4, ah, bh + 2);
                mma_bf16(C3 + nfp * 8 + 4, ah, bl + 2);
                mma_bf16(C3 + nfp * 8 + 4, al, bh + 2);
            }
        }
        __syncthreads();   // before restaging A2c / rewriting H
    }

    // ---- Phase 4: softmax over 16 neighbors (register fragments + shfl) ----
    {
        int q = w & 7;
#pragma unroll
        for (int nf = 0; nf < 4; nf++) {
            int c = n0w + nf * 8 + 2 * (lane & 3);
            float2 b2 = *(const float2*)(ab2 + c);
            float s00 = C3[nf * 4 + 0] + b2.x;
            float s01 = C3[nf * 4 + 1] + b2.y;
            float s10 = C3[nf * 4 + 2] + b2.x;
            float s11 = C3[nf * 4 + 3] + b2.y;
            float m0 = fmaxf(s00, s10);
            float m1 = fmaxf(s01, s11);
#pragma unroll
            for (int msk = 4; msk <= 16; msk <<= 1) {
                m0 = fmaxf(m0, __shfl_xor_sync(0xffffffffu, m0, msk));
                m1 = fmaxf(m1, __shfl_xor_sync(0xffffffffu, m1, msk));
            }
            float e00 = __expf(s00 - m0), e10 = __expf(s10 - m0);
            float e01 = __expf(s01 - m1), e11 = __expf(s11 - m1);
            float2 vgA = *(const float2*)(VG + rowA * 64 + c);
            float2 vgB = *(const float2*)(VG + rowB * 64 + c);
            float sum0 = e00 + e10, sum1 = e01 + e11;
            float agg0 = e00 * vgA.x + e10 * vgB.x;
            float agg1 = e01 * vgA.y + e11 * vgB.y;
#pragma unroll
            for (int msk = 4; msk <= 16; msk <<= 1) {
                sum0 += __shfl_xor_sync(0xffffffffu, sum0, msk);
                sum1 += __shfl_xor_sync(0xffffffffu, sum1, msk);
                agg0 += __shfl_xor_sync(0xffffffffu, agg0, msk);
                agg1 += __shfl_xor_sync(0xffffffffu, agg1, msk);
            }
            if (lane < 4) {
                float2 o = make_float2(agg0 / sum0, agg1 / sum1);
                *(float2*)(out + (ib + q) * 64 + c) = o;
            }
        }
    }
}

// ---------------------------------------------------------------------------
extern "C" void kernel_launch(void* const* d_in, const int* in_sizes, int n_in,
                              void* d_out, int out_size) {
    const float* x   = (const float*)d_in[0];
    const float* pos = (const float*)d_in[1];
    const float* Wq  = (const float*)d_in[2];
    const float* Wk  = (const float*)d_in[3];
    const float* Wv  = (const float*)d_in[4];
    const float* P1  = (const float*)d_in[5];
    const float* pb1 = (const float*)d_in[6];
    const float* P2  = (const float*)d_in[7];
    const float* pb2 = (const float*)d_in[8];
    const float* A1  = (const float*)d_in[9];
    const float* ab1 = (const float*)d_in[10];
    const float* A2  = (const float*)d_in[11];
    const float* ab2 = (const float*)d_in[12];
    float* out = (float*)d_out;

    cudaFuncSetAttribute(fused_kernel, cudaFuncAttributeMaxDynamicSharedMemorySize,
                         SMEM_BYTES);
    fused_kernel<<<GRID, NT, SMEM_BYTES>>>(
        x, pos, Wq, Wk, Wv, P1, pb1, P2, pb2, A1, ab1, A2, ab2, out);
}